// round 1
// baseline (speedup 1.0000x reference)
#include <cuda_runtime.h>
#include <math.h>

// Problem constants (fixed shapes)
#define BATCH 4
#define TLEN  1024
#define CH    512
#define DH    16
#define NROWS (BATCH*TLEN)   // 4096
#define OUTS  48             // k(16) | v(16) | r(16)
#define OCH   64

// Scratch (device globals — no allocation allowed)
__device__ float g_k[NROWS*DH];
__device__ float g_v[NROWS*DH];
__device__ float g_r[NROWS*DH];
__device__ float g_sumk[NROWS*DH];
__device__ float g_kvmean[BATCH*DH];
__device__ float g_wsum[TLEN];

// ---------------------------------------------------------------------------
// Kernel 1: w_sum[u] = alpha[u] * sum_{d=0}^{T-1-u} time_w[T-1-d] * beta[u+d]
// One warp per u. 32 blocks x 1024 threads.
// ---------------------------------------------------------------------------
__global__ void wsum_kernel(const float* __restrict__ time_w,
                            const float* __restrict__ alpha,
                            const float* __restrict__ beta) {
    int tid  = threadIdx.x;
    int lane = tid & 31;
    int u    = blockIdx.x * 32 + (tid >> 5);
    float s = 0.f;
    int dmax = TLEN - 1 - u;
    for (int d = lane; d <= dmax; d += 32)
        s += time_w[TLEN - 1 - d] * beta[u + d];
    #pragma unroll
    for (int off = 16; off > 0; off >>= 1)
        s += __shfl_down_sync(0xFFFFFFFFu, s, off);
    if (lane == 0)
        g_wsum[u] = alpha[u] * s;
}

// ---------------------------------------------------------------------------
// Kernel 2: projections. kvr = xx @ [Wk;Wv;Wr]^T + bias, with the time shift
// on the first 256 channels applied at load time.  Tiled smem GEMM:
//   block tile: 32 rows x 48 outs, K-chunk 64, 256 threads,
//   thread tile: 3 outs x 2 rows.
// Grid: 128 blocks (one wave on 148 SMs).
// ---------------------------------------------------------------------------
#define KC 64
#define RPB 32
#define XPAD 36   // 32 rows + pad (keeps LDS.64 conflict-free & aligned)

__global__ __launch_bounds__(256) void proj_kernel(
    const float* __restrict__ x,
    const float* __restrict__ Wk, const float* __restrict__ bk,
    const float* __restrict__ Wv, const float* __restrict__ bv,
    const float* __restrict__ Wr, const float* __restrict__ br)
{
    __shared__ float Ws[OUTS][KC];    // 12 KB
    __shared__ float Xs[KC][XPAD];    // 9 KB

    int tid  = threadIdx.x;
    int row0 = blockIdx.x * RPB;

    int rx = tid & 15;        // 16 row-groups * 2 rows
    int oy = tid >> 4;        // 16 out-groups * 3 outs
    int rl0 = rx * 2;
    int o0  = oy * 3;

    float acc[3][2];
    #pragma unroll
    for (int j = 0; j < 3; j++) { acc[j][0] = 0.f; acc[j][1] = 0.f; }

    for (int kc = 0; kc < CH; kc += KC) {
        // --- load weight tile, Ws[out][kk] <- W*[out][kc+kk]  (coalesced) ---
        #pragma unroll
        for (int it = 0; it < (OUTS*KC)/256; it++) {
            int e  = tid + it * 256;
            int kk = e & (KC - 1);
            int out = e >> 6;
            const float* wsrc = (out < 16) ? (Wk + out * CH)
                              : (out < 32) ? (Wv + (out - 16) * CH)
                                           : (Wr + (out - 32) * CH);
            Ws[out][kk] = wsrc[kc + kk];
        }
        // --- load x tile with time shift, Xs[kk][row] ---
        #pragma unroll
        for (int it = 0; it < (RPB*KC)/256; it++) {
            int e   = tid + it * 256;
            int kk  = e & (KC - 1);
            int rl  = e >> 6;
            int c   = kc + kk;
            int row = row0 + rl;
            int t   = row & (TLEN - 1);
            float val;
            if (c < CH/2) {
                val = (t > 0) ? x[(row - 1) * CH + c] : 0.f;
            } else {
                val = x[row * CH + c];
            }
            Xs[kk][rl] = val;
        }
        __syncthreads();

        #pragma unroll
        for (int kk = 0; kk < KC; kk++) {
            float2 xv = *(const float2*)&Xs[kk][rl0];
            float w0 = Ws[o0 + 0][kk];
            float w1 = Ws[o0 + 1][kk];
            float w2 = Ws[o0 + 2][kk];
            acc[0][0] += w0 * xv.x; acc[0][1] += w0 * xv.y;
            acc[1][0] += w1 * xv.x; acc[1][1] += w1 * xv.y;
            acc[2][0] += w2 * xv.x; acc[2][1] += w2 * xv.y;
        }
        __syncthreads();
    }

    // epilogue: bias, exp-clip for k part, scatter to g_k/g_v/g_r
    #pragma unroll
    for (int j = 0; j < 3; j++) {
        int out   = o0 + j;
        int d     = out & 15;
        int which = out >> 4;
        float bias = (which == 0) ? bk[d] : (which == 1) ? bv[d] : br[d];
        #pragma unroll
        for (int i = 0; i < 2; i++) {
            int row = row0 + rl0 + i;
            float val = acc[j][i] + bias;
            if (which == 0) {
                val = expf(fminf(fmaxf(val, -60.f), 30.f));
                g_k[row * DH + d] = val;
            } else if (which == 1) {
                g_v[row * DH + d] = val;
            } else {
                g_r[row * DH + d] = val;
            }
        }
    }
}

// ---------------------------------------------------------------------------
// Kernel 3: per (b,d): inclusive cumsum of k over t -> g_sumk,
//           and kv_mean[b,d] = mean_t(k*v).  Deterministic (no atomics).
// Grid: 64 blocks x 1024 threads.
// ---------------------------------------------------------------------------
__global__ __launch_bounds__(1024) void scan_kernel() {
    __shared__ float wsh[32];

    int bd = blockIdx.x;
    int b  = bd >> 4;
    int d  = bd & 15;
    int t  = threadIdx.x;
    int lane = t & 31;
    int wid  = t >> 5;

    int idx = ((b << 10) + t) * DH + d;
    float kval = g_k[idx];
    float vval = g_v[idx];

    // inclusive warp scan
    float val = kval;
    #pragma unroll
    for (int off = 1; off < 32; off <<= 1) {
        float n = __shfl_up_sync(0xFFFFFFFFu, val, off);
        if (lane >= off) val += n;
    }
    if (lane == 31) wsh[wid] = val;
    __syncthreads();
    if (wid == 0) {
        float s = wsh[lane];
        #pragma unroll
        for (int off = 1; off < 32; off <<= 1) {
            float n = __shfl_up_sync(0xFFFFFFFFu, s, off);
            if (lane >= off) s += n;
        }
        wsh[lane] = s;
    }
    __syncthreads();
    float prefix = (wid > 0) ? wsh[wid - 1] : 0.f;
    g_sumk[idx] = val + prefix;
    __syncthreads();

    // kv reduction
    float kv = kval * vval;
    #pragma unroll
    for (int off = 16; off > 0; off >>= 1)
        kv += __shfl_down_sync(0xFFFFFFFFu, kv, off);
    if (lane == 0) wsh[wid] = kv;
    __syncthreads();
    if (wid == 0) {
        float s = wsh[lane];
        #pragma unroll
        for (int off = 16; off > 0; off >>= 1)
            s += __shfl_down_sync(0xFFFFFFFFu, s, off);
        if (lane == 0)
            g_kvmean[(b << 4) + d] = s * (1.0f / (float)TLEN);
    }
}

// ---------------------------------------------------------------------------
// Kernel 4: out[b,t,o] = (sum_d rwkv[d]*Wo[o][d] + bo[o]) * gamma[t]
//   rwkv[d] = r * w_sum[t] * kv_mean[b,d] / (sum_k + 1e-8)
// 4 rows x 64 outs per block, 256 threads.  Grid: 1024 blocks.
// ---------------------------------------------------------------------------
__global__ __launch_bounds__(256) void out_kernel(
    const float* __restrict__ Wo, const float* __restrict__ bo,
    const float* __restrict__ gamma, float* __restrict__ out)
{
    int tid = threadIdx.x;
    int o   = tid & 63;
    int rl  = tid >> 6;
    int row = blockIdx.x * 4 + rl;
    int b   = row >> 10;
    int t   = row & (TLEN - 1);

    // Wo row into registers (16 floats, vector loads)
    const float4* wop = (const float4*)(Wo + o * DH);
    float4 w0 = wop[0], w1 = wop[1], w2 = wop[2], w3 = wop[3];
    float wor[16] = {w0.x,w0.y,w0.z,w0.w, w1.x,w1.y,w1.z,w1.w,
                     w2.x,w2.y,w2.z,w2.w, w3.x,w3.y,w3.z,w3.w};

    float ws = g_wsum[t];
    const float4* rp  = (const float4*)(g_r   + row * DH);
    const float4* skp = (const float4*)(g_sumk + row * DH);
    const float4* kmp = (const float4*)(g_kvmean + (b << 4));

    float acc = 0.f;
    #pragma unroll
    for (int q = 0; q < 4; q++) {
        float4 rv = rp[q];
        float4 sk = skp[q];
        float4 km = kmp[q];
        acc += (rv.x * ws * km.x / (sk.x + 1e-8f)) * wor[4*q+0];
        acc += (rv.y * ws * km.y / (sk.y + 1e-8f)) * wor[4*q+1];
        acc += (rv.z * ws * km.z / (sk.z + 1e-8f)) * wor[4*q+2];
        acc += (rv.w * ws * km.w / (sk.w + 1e-8f)) * wor[4*q+3];
    }
    out[row * OCH + o] = (acc + bo[o]) * gamma[t];
}

// ---------------------------------------------------------------------------
extern "C" void kernel_launch(void* const* d_in, const int* in_sizes, int n_in,
                              void* d_out, int out_size)
{
    const float* x      = (const float*)d_in[0];
    const float* time_w = (const float*)d_in[1];
    const float* alpha  = (const float*)d_in[2];   // [1,1,TT] flat
    const float* beta   = (const float*)d_in[3];   // [1,TT,1] flat
    const float* gamma  = (const float*)d_in[4];   // [TT,1]   flat
    const float* Wk     = (const float*)d_in[5];
    const float* bk     = (const float*)d_in[6];
    const float* Wv     = (const float*)d_in[7];
    const float* bv     = (const float*)d_in[8];
    const float* Wr     = (const float*)d_in[9];
    const float* br     = (const float*)d_in[10];
    const float* Wo     = (const float*)d_in[11];
    const float* bo     = (const float*)d_in[12];
    float* out = (float*)d_out;

    wsum_kernel<<<32, 1024>>>(time_w, alpha, beta);
    proj_kernel<<<NROWS / RPB, 256>>>(x, Wk, bk, Wv, bv, Wr, br);
    scan_kernel<<<BATCH * DH, 1024>>>();
    out_kernel<<<NROWS / 4, 256>>>(Wo, bo, gamma, out);
}